// round 3
// baseline (speedup 1.0000x reference)
#include <cuda_runtime.h>
#include <cuda_bf16.h>
#include <cstdint>

// Integration_4123168604342
// x: (T=128, B=4, E=10000, F=16) f32, dummy_index: int scalar
// out: (128, 4, 10000, 15) f32 = tanh(cumsum_T(f * dt))
//
// R3: float4 mapping — 4 threads per (b,e) group, each thread owns 4 channels
// via LDG.128. 4-deep register pipeline => 2KB/warp of reads in flight
// (4x the scalar version) to close the DRAM latency-saturation gap.

#define T_DIM   128
#define B_DIM   4
#define E_DIM   10000
#define F_DIM   16
#define FO_DIM  15
#define BE_DIM  (B_DIM * E_DIM)               // 40000 groups
#define STRIDE_T   ((size_t)BE_DIM * F_DIM)   // 640000 floats per t (input)
#define STRIDE_T4  (STRIDE_T / 4)             // 160000 float4 per t
#define STRIDE_TO  ((size_t)BE_DIM * FO_DIM)  // 600000 floats per t (output)

__device__ __forceinline__ float tanh_fast(float x) {
    float y;
    asm("tanh.approx.f32 %0, %1;" : "=f"(y) : "f"(x));
    return y;
}

// Select component (d & 3) of a float4 with uniform predicates (3 SELs).
__device__ __forceinline__ float sel4(float4 v, bool p1, bool p2) {
    float a = p1 ? v.y : v.x;
    float b = p1 ? v.w : v.z;
    return p2 ? b : a;
}

__global__ __launch_bounds__(128)
void integration_kernel(const float* __restrict__ x,
                        const int* __restrict__ didx,
                        float* __restrict__ out) {
    const int gid   = blockIdx.x * blockDim.x + threadIdx.x;  // 0..159999
    const int group = gid >> 2;       // (b,e) flat index, 0..39999
    const int c     = gid & 3;        // which float4 chunk of the 16 channels

    const int d = *didx;              // dummy (time) channel, uniform
    const bool p1 = (d & 1) != 0;
    const bool p2 = (d & 2) != 0;
    const int d_hi = d >> 2;          // owner thread within 4-lane group

    // This thread's 4 input channels: 4c .. 4c+3
    const int ch0 = 4 * c;
    const bool skip0 = (ch0     == d);
    const bool skip1 = (ch0 + 1 == d);
    const bool skip2 = (ch0 + 2 == d);
    const bool skip3 = (ch0 + 3 == d);
    const int off0 = ch0     - (ch0     > d ? 1 : 0);
    const int off1 = ch0 + 1 - (ch0 + 1 > d ? 1 : 0);
    const int off2 = ch0 + 2 - (ch0 + 2 > d ? 1 : 0);
    const int off3 = ch0 + 3 - (ch0 + 3 > d ? 1 : 0);

    const float4* __restrict__ xp = (const float4*)x + (size_t)group * 4 + c;
    float* __restrict__ opb = out + (size_t)group * FO_DIM;

    // ---- prologue: rows 0..3 in flight together ----
    float4 b0 = xp[0];
    float4 b1 = xp[STRIDE_T4];
    float4 b2 = xp[2 * STRIDE_T4];
    float4 b3 = xp[3 * STRIDE_T4];

    const float t0 = __shfl_sync(0xFFFFFFFFu, sel4(b0, p1, p2), d_hi, 4);
    const float t1 = __shfl_sync(0xFFFFFFFFu, sel4(b1, p1, p2), d_hi, 4);

    // t = 0: dt0 = t[0] + t[1]
    const float dt0 = t0 + t1;
    float acc0 = b0.x * dt0;
    float acc1 = b0.y * dt0;
    float acc2 = b0.z * dt0;
    float acc3 = b0.w * dt0;
    {
        float* o = opb;
        if (!skip0) o[off0] = tanh_fast(acc0);
        if (!skip1) o[off1] = tanh_fast(acc1);
        if (!skip2) o[off2] = tanh_fast(acc2);
        if (!skip3) o[off3] = tanh_fast(acc3);
    }
    float prev_t = t0;

#define PROCESS_ROW(bv, trow) do {                                         \
        const float tl = sel4(bv, p1, p2);                                 \
        const float tc = __shfl_sync(0xFFFFFFFFu, tl, d_hi, 4);            \
        const float dt = tc - prev_t;                                      \
        acc0 = fmaf(bv.x, dt, acc0);                                       \
        acc1 = fmaf(bv.y, dt, acc1);                                       \
        acc2 = fmaf(bv.z, dt, acc2);                                       \
        acc3 = fmaf(bv.w, dt, acc3);                                       \
        float* o = opb + (size_t)(trow) * STRIDE_TO;                       \
        if (!skip0) o[off0] = tanh_fast(acc0);                             \
        if (!skip1) o[off1] = tanh_fast(acc1);                             \
        if (!skip2) o[off2] = tanh_fast(acc2);                             \
        if (!skip3) o[off3] = tanh_fast(acc3);                             \
        prev_t = tc;                                                       \
    } while (0)

    // ---- steady state: process rows base..base+3, prefetch base+4..base+7 ----
    #pragma unroll 1
    for (int base = 0; base < T_DIM - 4; base += 4) {
        // front-batched, unguarded prefetch of the next 4 rows (MLP_p1 = 4 x LDG.128)
        const float4* p = xp + (size_t)(base + 4) * STRIDE_T4;
        float4 n0 = p[0];
        float4 n1 = p[STRIDE_T4];
        float4 n2 = p[2 * STRIDE_T4];
        float4 n3 = p[3 * STRIDE_T4];

        if (base > 0) PROCESS_ROW(b0, base);
        PROCESS_ROW(b1, base + 1);
        PROCESS_ROW(b2, base + 2);
        PROCESS_ROW(b3, base + 3);

        b0 = n0; b1 = n1; b2 = n2; b3 = n3;
    }

    // ---- epilogue: rows 124..127 ----
    PROCESS_ROW(b0, T_DIM - 4);
    PROCESS_ROW(b1, T_DIM - 3);
    PROCESS_ROW(b2, T_DIM - 2);
    PROCESS_ROW(b3, T_DIM - 1);

#undef PROCESS_ROW
}

extern "C" void kernel_launch(void* const* d_in, const int* in_sizes, int n_in,
                              void* d_out, int out_size) {
    const float* x   = (const float*)d_in[0];
    const int* didx  = (const int*)d_in[1];
    float* out       = (float*)d_out;

    const int total_threads = BE_DIM * 4;         // 160000
    const int block = 128;
    const int grid = total_threads / block;       // 1250 exactly
    integration_kernel<<<grid, block>>>(x, didx, out);
}

// round 4
// speedup vs baseline: 1.4900x; 1.4900x over previous
#include <cuda_runtime.h>
#include <cuda_bf16.h>
#include <cstdint>

// Integration_4123168604342
// x: (T=128, B=4, E=10000, F=16) f32, dummy_index: int scalar
// out: (128, 4, 10000, 15) f32 = tanh(cumsum_T(f * dt))
//
// R4: back to the R2 scalar mapping (16-lane group per (b,e), lane=channel,
// high occupancy, minimal L1 wavefronts), but with a DEPTH-8 register
// pipeline: 1KB/warp of reads in flight to saturate DRAM.

#define T_DIM   128
#define B_DIM   4
#define E_DIM   10000
#define F_DIM   16
#define FO_DIM  15
#define BE_DIM  (B_DIM * E_DIM)               // 40000 groups
#define STRIDE_T   ((size_t)BE_DIM * F_DIM)   // 640000 floats per t (input)
#define STRIDE_TO  ((size_t)BE_DIM * FO_DIM)  // 600000 floats per t (output)

__device__ __forceinline__ float tanh_fast(float x) {
    float y;
    asm("tanh.approx.f32 %0, %1;" : "=f"(y) : "f"(x));
    return y;
}

__global__ __launch_bounds__(256)
void integration_kernel(const float* __restrict__ x,
                        const int* __restrict__ didx,
                        float* __restrict__ out) {
    const int gid   = blockIdx.x * blockDim.x + threadIdx.x;
    const int group = gid >> 4;       // (b,e) flat index
    const int lane  = gid & 15;       // channel
    if (group >= BE_DIM) return;

    const int d = *didx;              // dummy (time) channel
    const bool is_t = (lane == d);
    const int oc = lane - (lane > d ? 1 : 0);   // output channel for non-t lanes

    const float* __restrict__ xp = x + (size_t)group * F_DIM + lane;
    float* __restrict__ op = out + (size_t)group * FO_DIM + oc;

    // ---- prologue: rows 0..7 in flight together (8 x LDG.32 front-batched) ----
    float b0 = xp[0];
    float b1 = xp[STRIDE_T];
    float b2 = xp[2 * STRIDE_T];
    float b3 = xp[3 * STRIDE_T];
    float b4 = xp[4 * STRIDE_T];
    float b5 = xp[5 * STRIDE_T];
    float b6 = xp[6 * STRIDE_T];
    float b7 = xp[7 * STRIDE_T];

    const float t0 = __shfl_sync(0xFFFFFFFFu, b0, d, 16);
    const float t1 = __shfl_sync(0xFFFFFFFFu, b1, d, 16);

    // t = 0: dt0 = t[0] + t[1]
    float acc = b0 * (t0 + t1);
    if (!is_t) op[0] = tanh_fast(acc);
    float prev_t = t0;

#define PROCESS_ROW(bv, trow) do {                                   \
        const float tc = __shfl_sync(0xFFFFFFFFu, (bv), d, 16);      \
        acc = fmaf((bv), tc - prev_t, acc);                          \
        if (!is_t) op[(size_t)(trow) * STRIDE_TO] = tanh_fast(acc);  \
        prev_t = tc;                                                 \
    } while (0)

    // ---- steady state: process rows base..base+7, prefetch base+8..base+15 ----
    #pragma unroll 1
    for (int base = 0; base < T_DIM - 8; base += 8) {
        const float* p = xp + (size_t)(base + 8) * STRIDE_T;
        float n0 = p[0];
        float n1 = p[STRIDE_T];
        float n2 = p[2 * STRIDE_T];
        float n3 = p[3 * STRIDE_T];
        float n4 = p[4 * STRIDE_T];
        float n5 = p[5 * STRIDE_T];
        float n6 = p[6 * STRIDE_T];
        float n7 = p[7 * STRIDE_T];

        if (base > 0) PROCESS_ROW(b0, base);
        PROCESS_ROW(b1, base + 1);
        PROCESS_ROW(b2, base + 2);
        PROCESS_ROW(b3, base + 3);
        PROCESS_ROW(b4, base + 4);
        PROCESS_ROW(b5, base + 5);
        PROCESS_ROW(b6, base + 6);
        PROCESS_ROW(b7, base + 7);

        b0 = n0; b1 = n1; b2 = n2; b3 = n3;
        b4 = n4; b5 = n5; b6 = n6; b7 = n7;
    }

    // ---- epilogue: rows 120..127 ----
    PROCESS_ROW(b0, T_DIM - 8);
    PROCESS_ROW(b1, T_DIM - 7);
    PROCESS_ROW(b2, T_DIM - 6);
    PROCESS_ROW(b3, T_DIM - 5);
    PROCESS_ROW(b4, T_DIM - 4);
    PROCESS_ROW(b5, T_DIM - 3);
    PROCESS_ROW(b6, T_DIM - 2);
    PROCESS_ROW(b7, T_DIM - 1);

#undef PROCESS_ROW
}

extern "C" void kernel_launch(void* const* d_in, const int* in_sizes, int n_in,
                              void* d_out, int out_size) {
    const float* x   = (const float*)d_in[0];
    const int* didx  = (const int*)d_in[1];
    float* out       = (float*)d_out;

    const int total_threads = BE_DIM * 16;        // 640000
    const int block = 256;
    const int grid = (total_threads + block - 1) / block;  // 2500
    integration_kernel<<<grid, block>>>(x, didx, out);
}

// round 5
// speedup vs baseline: 1.5122x; 1.0149x over previous
#include <cuda_runtime.h>
#include <cuda_bf16.h>
#include <cstdint>

// Integration_4123168604342
// x: (T=128, B=4, E=10000, F=16) f32, dummy_index: int scalar
// out: (128, 4, 10000, 15) f32 = tanh(cumsum_T(f * dt))
//
// R5: rotating-buffer pipeline, depth 16. Consume b[k] for row t, then
// immediately reload b[k] from row t+16. Live regs = 16 buffers (no
// double-buffering), so ptxas cannot re-serialize the schedule to save
// registers the way it did to R4's front-batched depth-8 version.
// Steady-state outstanding LDGs/warp = 16 -> ~2KB/warp in flight.

#define T_DIM   128
#define B_DIM   4
#define E_DIM   10000
#define F_DIM   16
#define FO_DIM  15
#define DEPTH   16
#define BE_DIM  (B_DIM * E_DIM)               // 40000 groups
#define STRIDE_T   ((size_t)BE_DIM * F_DIM)   // 640000 floats per t (input)
#define STRIDE_TO  ((size_t)BE_DIM * FO_DIM)  // 600000 floats per t (output)

__device__ __forceinline__ float tanh_fast(float x) {
    float y;
    asm("tanh.approx.f32 %0, %1;" : "=f"(y) : "f"(x));
    return y;
}

__global__ __launch_bounds__(256)
void integration_kernel(const float* __restrict__ x,
                        const int* __restrict__ didx,
                        float* __restrict__ out) {
    const int gid   = blockIdx.x * blockDim.x + threadIdx.x;
    const int group = gid >> 4;       // (b,e) flat index
    const int lane  = gid & 15;       // channel
    if (group >= BE_DIM) return;

    const int d = *didx;              // dummy (time) channel
    const bool is_t = (lane == d);
    const int oc = lane - (lane > d ? 1 : 0);   // output channel for non-t lanes

    const float* __restrict__ xp = x + (size_t)group * F_DIM + lane;
    float* __restrict__ op = out + (size_t)group * FO_DIM + oc;

    // ---- prologue: rows 0..15 in flight ----
    float b0  = xp[0];
    float b1  = xp[STRIDE_T];
    float b2  = xp[2 * STRIDE_T];
    float b3  = xp[3 * STRIDE_T];
    float b4  = xp[4 * STRIDE_T];
    float b5  = xp[5 * STRIDE_T];
    float b6  = xp[6 * STRIDE_T];
    float b7  = xp[7 * STRIDE_T];
    float b8  = xp[8 * STRIDE_T];
    float b9  = xp[9 * STRIDE_T];
    float b10 = xp[10 * STRIDE_T];
    float b11 = xp[11 * STRIDE_T];
    float b12 = xp[12 * STRIDE_T];
    float b13 = xp[13 * STRIDE_T];
    float b14 = xp[14 * STRIDE_T];
    float b15 = xp[15 * STRIDE_T];

    const float t0 = __shfl_sync(0xFFFFFFFFu, b0, d, 16);
    const float t1 = __shfl_sync(0xFFFFFFFFu, b1, d, 16);

    // t = 0: dt0 = t[0] + t[1]
    float acc = b0 * (t0 + t1);
    if (!is_t) op[0] = tanh_fast(acc);
    float prev_t = t0;

    // consume row (trow) from buffer bv, then reload bv from row trow+DEPTH
#define STEP(bv, k) do {                                                    \
        const float tc = __shfl_sync(0xFFFFFFFFu, (bv), d, 16);             \
        acc = fmaf((bv), tc - prev_t, acc);                                 \
        if (!is_t) op[(size_t)(base + (k)) * STRIDE_TO] = tanh_fast(acc);   \
        prev_t = tc;                                                        \
        (bv) = xp[(size_t)(base + (k) + DEPTH) * STRIDE_T];                 \
    } while (0)

#define STEP_NOLOAD(bv, k) do {                                             \
        const float tc = __shfl_sync(0xFFFFFFFFu, (bv), d, 16);             \
        acc = fmaf((bv), tc - prev_t, acc);                                 \
        if (!is_t) op[(size_t)(base + (k)) * STRIDE_TO] = tanh_fast(acc);   \
        prev_t = tc;                                                        \
    } while (0)

    // ---- steady state: 7 iterations (rows 0..111 consumed, 16..127 loaded) ----
    #pragma unroll 1
    for (int base = 0; base < T_DIM - DEPTH; base += DEPTH) {
        if (base > 0) STEP(b0, 0);
        else          b0 = xp[(size_t)DEPTH * STRIDE_T];   // row 0 already done
        STEP(b1,  1);
        STEP(b2,  2);
        STEP(b3,  3);
        STEP(b4,  4);
        STEP(b5,  5);
        STEP(b6,  6);
        STEP(b7,  7);
        STEP(b8,  8);
        STEP(b9,  9);
        STEP(b10, 10);
        STEP(b11, 11);
        STEP(b12, 12);
        STEP(b13, 13);
        STEP(b14, 14);
        STEP(b15, 15);
    }

    // ---- epilogue: rows 112..127, no more loads ----
    {
        const int base = T_DIM - DEPTH;
        STEP_NOLOAD(b0,  0);
        STEP_NOLOAD(b1,  1);
        STEP_NOLOAD(b2,  2);
        STEP_NOLOAD(b3,  3);
        STEP_NOLOAD(b4,  4);
        STEP_NOLOAD(b5,  5);
        STEP_NOLOAD(b6,  6);
        STEP_NOLOAD(b7,  7);
        STEP_NOLOAD(b8,  8);
        STEP_NOLOAD(b9,  9);
        STEP_NOLOAD(b10, 10);
        STEP_NOLOAD(b11, 11);
        STEP_NOLOAD(b12, 12);
        STEP_NOLOAD(b13, 13);
        STEP_NOLOAD(b14, 14);
        STEP_NOLOAD(b15, 15);
    }

#undef STEP
#undef STEP_NOLOAD
}

extern "C" void kernel_launch(void* const* d_in, const int* in_sizes, int n_in,
                              void* d_out, int out_size) {
    const float* x   = (const float*)d_in[0];
    const int* didx  = (const int*)d_in[1];
    float* out       = (float*)d_out;

    const int total_threads = BE_DIM * 16;        // 640000
    const int block = 256;
    const int grid = (total_threads + block - 1) / block;  // 2500
    integration_kernel<<<grid, block>>>(x, didx, out);
}